// round 5
// baseline (speedup 1.0000x reference)
#include <cuda_runtime.h>

// WaveletMask: fused Haar fwd -> mosaic weight multiply -> Haar inv.
// H=128, HB=64. One thread per FOUR adjacent 2x2 blocks (all-float4 path).
// 1024 threads = 4 blocks x 256 threads.
// Per thread: 4x LDG.128 (x), 4x LDG.128 (w), 4x STG.128 (out). All independent.

#define H 128
#define HB 64

__global__ void __launch_bounds__(256, 1) wavelet_mask_kernel(
    const float* __restrict__ x,
    const float* __restrict__ w,
    float* __restrict__ out)
{
    const int t = blockIdx.x * 256 + threadIdx.x;  // 0..1023
    const int i = t >> 4;                          // block row 0..63
    const int q = t & 15;                          // group col 0..15 (block cols 4q..4q+3)

    const int xoff = (2 * i) * H + 8 * q;

    // Two x rows, 8 floats each (4 blocks of 2x2)
    const float4 t0 = *reinterpret_cast<const float4*>(x + xoff);
    const float4 t1 = *reinterpret_cast<const float4*>(x + xoff + 4);
    const float4 b0 = *reinterpret_cast<const float4*>(x + xoff + H);
    const float4 b1 = *reinterpret_cast<const float4*>(x + xoff + H + 4);

    // Mosaic weights for block cols 4q..4q+3 (contiguous per quadrant)
    const float4 wll = *reinterpret_cast<const float4*>(w + i * H + 4 * q);
    const float4 wlh = *reinterpret_cast<const float4*>(w + i * H + 4 * q + HB);
    const float4 whl = *reinterpret_cast<const float4*>(w + (i + HB) * H + 4 * q);
    const float4 whh = *reinterpret_cast<const float4*>(w + (i + HB) * H + 4 * q + HB);

    const float top[8] = {t0.x, t0.y, t0.z, t0.w, t1.x, t1.y, t1.z, t1.w};
    const float bot[8] = {b0.x, b0.y, b0.z, b0.w, b1.x, b1.y, b1.z, b1.w};
    const float wl[4]  = {wll.x, wll.y, wll.z, wll.w};
    const float wh[4]  = {wlh.x, wlh.y, wlh.z, wlh.w};
    const float vl[4]  = {whl.x, whl.y, whl.z, whl.w};
    const float vh[4]  = {whh.x, whh.y, whh.z, whh.w};

    float ot[8], ob[8];

#pragma unroll
    for (int k = 0; k < 4; k++) {
        const float a = top[2 * k], bb = top[2 * k + 1];
        const float c = bot[2 * k], d  = bot[2 * k + 1];
        const float apb = a + bb, amb = a - bb;
        const float cpd = c + d,  cmd = c - d;
        const float ll = (apb + cpd) * 0.5f * wl[k];
        const float lh = (apb - cpd) * 0.5f * wh[k];
        const float hl = (amb + cmd) * 0.5f * vl[k];
        const float hh = (amb - cmd) * 0.5f * vh[k];
        const float lp = ll + lh, lm = ll - lh;
        const float hp = hl + hh, hm = hl - hh;
        ot[2 * k]     = (lp + hp) * 0.5f;
        ot[2 * k + 1] = (lp - hp) * 0.5f;
        ob[2 * k]     = (lm + hm) * 0.5f;
        ob[2 * k + 1] = (lm - hm) * 0.5f;
    }

    *reinterpret_cast<float4*>(out + xoff)         = make_float4(ot[0], ot[1], ot[2], ot[3]);
    *reinterpret_cast<float4*>(out + xoff + 4)     = make_float4(ot[4], ot[5], ot[6], ot[7]);
    *reinterpret_cast<float4*>(out + xoff + H)     = make_float4(ob[0], ob[1], ob[2], ob[3]);
    *reinterpret_cast<float4*>(out + xoff + H + 4) = make_float4(ob[4], ob[5], ob[6], ob[7]);
}

extern "C" void kernel_launch(void* const* d_in, const int* in_sizes, int n_in,
                              void* d_out, int out_size)
{
    const float* x = (const float*)d_in[0];
    const float* w = (const float*)d_in[1];
    float* out = (float*)d_out;
    wavelet_mask_kernel<<<4, 256>>>(x, w, out);
}

// round 6
// speedup vs baseline: 1.1316x; 1.1316x over previous
#include <cuda_runtime.h>

// WaveletMask: fused Haar fwd -> mosaic weight multiply -> Haar inv.
// H=128, HB=64. One thread per TWO adjacent 2x2 blocks (float4 x/out, float2 w).
// 2048 threads = 32 blocks x 64 threads (2 warps/block, ~32 SMs active).
// Per thread: 2x LDG.128 (x), 4x LDG.64 (w), 2x STG.128 (out). All independent.

#define H 128
#define HB 64

__global__ void __launch_bounds__(64, 1) wavelet_mask_kernel(
    const float* __restrict__ x,
    const float* __restrict__ w,
    float* __restrict__ out)
{
    const int t = blockIdx.x * 64 + threadIdx.x;   // 0..2047
    const int i = t >> 5;                          // block row 0..63
    const int q = t & 31;                          // quad-column 0..31 (block cols 2q, 2q+1)

    const int xoff = (2 * i) * H + 4 * q;
    // Two adjacent 2x2 input blocks, vectorized
    const float4 top = *reinterpret_cast<const float4*>(x + xoff);
    const float4 bot = *reinterpret_cast<const float4*>(x + xoff + H);

    // Mosaic weights for block cols 2q and 2q+1 (contiguous per quadrant)
    const float2 wll = *reinterpret_cast<const float2*>(w + i * H + 2 * q);
    const float2 wlh = *reinterpret_cast<const float2*>(w + i * H + 2 * q + HB);
    const float2 whl = *reinterpret_cast<const float2*>(w + (i + HB) * H + 2 * q);
    const float2 whh = *reinterpret_cast<const float2*>(w + (i + HB) * H + 2 * q + HB);

    float4 otop, obot;

    // ---- block 0: (top.x, top.y, bot.x, bot.y) ----
    {
        const float apb = top.x + top.y, amb = top.x - top.y;
        const float cpd = bot.x + bot.y, cmd = bot.x - bot.y;
        const float ll = (apb + cpd) * 0.5f * wll.x;
        const float lh = (apb - cpd) * 0.5f * wlh.x;
        const float hl = (amb + cmd) * 0.5f * whl.x;
        const float hh = (amb - cmd) * 0.5f * whh.x;
        const float lp = ll + lh, lm = ll - lh;
        const float hp = hl + hh, hm = hl - hh;
        otop.x = (lp + hp) * 0.5f;
        otop.y = (lp - hp) * 0.5f;
        obot.x = (lm + hm) * 0.5f;
        obot.y = (lm - hm) * 0.5f;
    }
    // ---- block 1: (top.z, top.w, bot.z, bot.w) ----
    {
        const float apb = top.z + top.w, amb = top.z - top.w;
        const float cpd = bot.z + bot.w, cmd = bot.z - bot.w;
        const float ll = (apb + cpd) * 0.5f * wll.y;
        const float lh = (apb - cpd) * 0.5f * wlh.y;
        const float hl = (amb + cmd) * 0.5f * whl.y;
        const float hh = (amb - cmd) * 0.5f * whh.y;
        const float lp = ll + lh, lm = ll - lh;
        const float hp = hl + hh, hm = hl - hh;
        otop.z = (lp + hp) * 0.5f;
        otop.w = (lp - hp) * 0.5f;
        obot.z = (lm + hm) * 0.5f;
        obot.w = (lm - hm) * 0.5f;
    }

    *reinterpret_cast<float4*>(out + xoff)     = otop;
    *reinterpret_cast<float4*>(out + xoff + H) = obot;
}

extern "C" void kernel_launch(void* const* d_in, const int* in_sizes, int n_in,
                              void* d_out, int out_size)
{
    const float* x = (const float*)d_in[0];
    const float* w = (const float*)d_in[1];
    float* out = (float*)d_out;
    wavelet_mask_kernel<<<32, 64>>>(x, w, out);
}